// round 3
// baseline (speedup 1.0000x reference)
#include <cuda_runtime.h>
#include <cuda_fp16.h>

#define NIN 7
#define H   32
#define TPB 128   // threads per block
#define SPT 4     // samples per thread

typedef unsigned long long u64;

// ---- f32x2 packed helpers (sm_100+ PTX) ----
__device__ __forceinline__ u64 pk2(float a, float b) {
    u64 r; asm("mov.b64 %0, {%1, %2};" : "=l"(r) : "f"(a), "f"(b)); return r;
}
__device__ __forceinline__ float2 upk2(u64 v) {
    float2 f; asm("mov.b64 {%0, %1}, %2;" : "=f"(f.x), "=f"(f.y) : "l"(v)); return f;
}
__device__ __forceinline__ u64 ffma2(u64 a, u64 b, u64 c) {
    u64 r; asm("fma.rn.f32x2 %0, %1, %2, %3;" : "=l"(r) : "l"(a), "l"(b), "l"(c)); return r;
}

// tanh(x) = 1 - 2/(exp(2x)+1); 2x MUFU, rel err ~1e-6, correct +/-1 saturation.
__device__ __forceinline__ float tanh_fast(float x) {
    float e = __expf(2.0f * x);
    return 1.0f - __fdividef(2.0f, e + 1.0f);
}

__global__ __launch_bounds__(TPB, 3)
void WarpTileMLP_kernel(const float* __restrict__ q,
                        const float* __restrict__ w0, const float* __restrict__ b0,
                        const float* __restrict__ w1, const float* __restrict__ b1,
                        const float* __restrict__ w2, const float* __restrict__ b2,
                        float* __restrict__ out)
{
    // Weights transposed to [i][h]: adjacent h adjacent in memory, so one
    // 128-bit broadcast shared load = 2 f32x2 weight pairs, reused by 4 samples.
    __shared__ __align__(16) float sw0[NIN * H];   // sw0[i*32 + h] = w0[h][i]
    __shared__ __align__(16) float sw1[H * H];     // sw1[i*32 + h] = w1[h][i]
    __shared__ __align__(16) float sb0[H];
    __shared__ __align__(16) float sb1[H];
    __shared__ __align__(16) float sw2[H];
    __shared__ float sb2s;

    const int tid = threadIdx.x;
    for (int k = tid; k < NIN * H; k += TPB) {
        int i = k >> 5, h = k & 31;
        sw0[k] = w0[h * NIN + i];
    }
    for (int k = tid; k < H * H; k += TPB) {
        int i = k >> 5, h = k & 31;
        sw1[k] = w1[h * H + i];
    }
    if (tid < H) { sb0[tid] = b0[tid]; sb1[tid] = b1[tid]; sw2[tid] = w2[tid]; }
    if (tid == 0) sb2s = b2[0];
    __syncthreads();

    const long t = (long)blockIdx.x * TPB + tid;

    // 4 samples = 28 contiguous floats = 7 aligned float4 loads (112B, 16B-aligned).
    const float4* qv4 = (const float4*)q;
    float v[4 * NIN];
#pragma unroll
    for (int j = 0; j < 7; ++j) {
        float4 p = __ldg(&qv4[t * 7 + j]);
        v[4 * j] = p.x; v[4 * j + 1] = p.y; v[4 * j + 2] = p.z; v[4 * j + 3] = p.w;
    }
    // v[s*7 + i] = input i of sample s

    const ulonglong2* sw0v = (const ulonglong2*)sw0;  // [i*8 + c]: floats i*32+4c..+3
    const ulonglong2* sw1v = (const ulonglong2*)sw1;
    const u64* sb0p = (const u64*)sb0;
    const u64* sb1p = (const u64*)sb1;
    const u64* sw2p = (const u64*)sw2;

    // Layer-0 activations, f16x2-compressed: zh[s][k] = (z_{2k}, z_{2k+1}).
    __half2 zh[SPT][16];

    // ---------------- Layer 0: 7 -> 32, in two 16-unit halves ----------------
#pragma unroll
    for (int half = 0; half < 2; ++half) {
        u64 acc[SPT][8];
#pragma unroll
        for (int p = 0; p < 8; ++p) {
            u64 bb = sb0p[half * 8 + p];
#pragma unroll
            for (int s = 0; s < SPT; ++s) acc[s][p] = bb;
        }
#pragma unroll
        for (int i = 0; i < NIN; ++i) {
            u64 xs[SPT];
#pragma unroll
            for (int s = 0; s < SPT; ++s) xs[s] = pk2(v[s * 7 + i], v[s * 7 + i]);
#pragma unroll
            for (int c = 0; c < 4; ++c) {
                ulonglong2 w = sw0v[i * 8 + half * 4 + c];
#pragma unroll
                for (int s = 0; s < SPT; ++s) {
                    acc[s][2 * c]     = ffma2(w.x, xs[s], acc[s][2 * c]);
                    acc[s][2 * c + 1] = ffma2(w.y, xs[s], acc[s][2 * c + 1]);
                }
            }
        }
        // tanh -> f16x2 pack (acc dies here)
#pragma unroll
        for (int s = 0; s < SPT; ++s)
#pragma unroll
            for (int p = 0; p < 8; ++p) {
                float2 a = upk2(acc[s][p]);
                zh[s][half * 8 + p] = __floats2half2_rn(tanh_fast(a.x), tanh_fast(a.y));
            }
    }

    // ------- Layer 1 (two 16-unit output halves) fused with Layer 2 ---------
    u64 o[SPT];
#pragma unroll
    for (int s = 0; s < SPT; ++s) o[s] = pk2(0.0f, 0.0f);

#pragma unroll
    for (int half = 0; half < 2; ++half) {
        u64 a1[SPT][8];
#pragma unroll
        for (int p = 0; p < 8; ++p) {
            u64 bb = sb1p[half * 8 + p];
#pragma unroll
            for (int s = 0; s < SPT; ++s) a1[s][p] = bb;
        }
#pragma unroll
        for (int k = 0; k < 16; ++k) {          // i = 2k, 2k+1
            u64 x0[SPT], x1[SPT];
#pragma unroll
            for (int s = 0; s < SPT; ++s) {
                float2 zz = __half22float2(zh[s][k]);
                x0[s] = pk2(zz.x, zz.x);
                x1[s] = pk2(zz.y, zz.y);
            }
#pragma unroll
            for (int c = 0; c < 4; ++c) {
                ulonglong2 w = sw1v[(2 * k) * 8 + half * 4 + c];
#pragma unroll
                for (int s = 0; s < SPT; ++s) {
                    a1[s][2 * c]     = ffma2(w.x, x0[s], a1[s][2 * c]);
                    a1[s][2 * c + 1] = ffma2(w.y, x0[s], a1[s][2 * c + 1]);
                }
            }
#pragma unroll
            for (int c = 0; c < 4; ++c) {
                ulonglong2 w = sw1v[(2 * k + 1) * 8 + half * 4 + c];
#pragma unroll
                for (int s = 0; s < SPT; ++s) {
                    a1[s][2 * c]     = ffma2(w.x, x1[s], a1[s][2 * c]);
                    a1[s][2 * c + 1] = ffma2(w.y, x1[s], a1[s][2 * c + 1]);
                }
            }
        }
        // tanh + layer-2 partial dot (a1 dies here)
#pragma unroll
        for (int p = 0; p < 8; ++p) {
            u64 wp = sw2p[half * 8 + p];
#pragma unroll
            for (int s = 0; s < SPT; ++s) {
                float2 a = upk2(a1[s][p]);
                u64 z1 = pk2(tanh_fast(a.x), tanh_fast(a.y));
                o[s] = ffma2(wp, z1, o[s]);
            }
        }
    }

    const float bias2 = sb2s;
    float4 r;
    { float2 a = upk2(o[0]); r.x = a.x + a.y + bias2; }
    { float2 a = upk2(o[1]); r.y = a.x + a.y + bias2; }
    { float2 a = upk2(o[2]); r.z = a.x + a.y + bias2; }
    { float2 a = upk2(o[3]); r.w = a.x + a.y + bias2; }

    ((float4*)out)[t] = r;
}

extern "C" void kernel_launch(void* const* d_in, const int* in_sizes, int n_in,
                              void* d_out, int out_size)
{
    const float* q  = (const float*)d_in[0];
    const float* w0 = (const float*)d_in[1];
    const float* b0 = (const float*)d_in[2];
    const float* w1 = (const float*)d_in[3];
    const float* b1 = (const float*)d_in[4];
    const float* w2 = (const float*)d_in[5];
    const float* b2 = (const float*)d_in[6];
    float* out = (float*)d_out;

    const int B = in_sizes[0] / NIN;              // 2097152
    const int blocks = B / (TPB * SPT);           // 4096

    WarpTileMLP_kernel<<<blocks, TPB>>>(q, w0, b0, w1, b1, w2, b2, out);
}

// round 4
// speedup vs baseline: 1.4367x; 1.4367x over previous
#include <cuda_runtime.h>

#define NIN 7
#define H   32
#define TPB 128   // threads per block
#define SPT 2     // samples per thread

typedef unsigned long long u64;

// ---- f32x2 packed helpers (sm_100+ PTX) ----
__device__ __forceinline__ u64 pk2(float a, float b) {
    u64 r; asm("mov.b64 %0, {%1, %2};" : "=l"(r) : "f"(a), "f"(b)); return r;
}
__device__ __forceinline__ float2 upk2(u64 v) {
    float2 f; asm("mov.b64 {%0, %1}, %2;" : "=f"(f.x), "=f"(f.y) : "l"(v)); return f;
}
__device__ __forceinline__ u64 ffma2(u64 a, u64 b, u64 c) {
    u64 r; asm("fma.rn.f32x2 %0, %1, %2, %3;" : "=l"(r) : "l"(a), "l"(b), "l"(c)); return r;
}

// Single-instruction MUFU.TANH (sm_75+): 1 SFU op, zero fma-pipe ops.
__device__ __forceinline__ float tanh_approx(float x) {
    float r; asm("tanh.approx.f32 %0, %1;" : "=f"(r) : "f"(x)); return r;
}

__global__ __launch_bounds__(TPB, 4)
void WarpTileMLP_kernel(const float* __restrict__ q,
                        const float* __restrict__ w0, const float* __restrict__ b0,
                        const float* __restrict__ w1, const float* __restrict__ b1,
                        const float* __restrict__ w2, const float* __restrict__ b2,
                        float* __restrict__ out)
{
    // Weights transposed to [i][h]: one 128-bit broadcast shared load
    // = 2 f32x2 weight pairs (4 adjacent hidden units).
    __shared__ __align__(16) float sw0[NIN * H];   // sw0[i*32 + h] = w0[h][i]
    __shared__ __align__(16) float sw1[H * H];     // sw1[i*32 + h] = w1[h][i]
    __shared__ __align__(16) float sb0[H];
    __shared__ __align__(16) float sb1[H];
    __shared__ __align__(16) float sw2[H];
    __shared__ float sb2s;

    const int tid = threadIdx.x;
    for (int k = tid; k < NIN * H; k += TPB) {
        int i = k >> 5, h = k & 31;
        sw0[k] = w0[h * NIN + i];
    }
    for (int k = tid; k < H * H; k += TPB) {
        int i = k >> 5, h = k & 31;
        sw1[k] = w1[h * H + i];
    }
    if (tid < H) { sb0[tid] = b0[tid]; sb1[tid] = b1[tid]; sw2[tid] = w2[tid]; }
    if (tid == 0) sb2s = b2[0];
    __syncthreads();

    const long t = (long)blockIdx.x * TPB + tid;

    // 2 samples = 14 contiguous floats = 7 aligned float2 loads.
    const float2* qv = (const float2*)q;
    float v[14];
#pragma unroll
    for (int j = 0; j < 7; ++j) {
        float2 p = __ldg(&qv[t * 7 + j]);
        v[2 * j] = p.x; v[2 * j + 1] = p.y;
    }
    // sample A = v[0..6], sample B = v[7..13]

    const ulonglong2* sw0v = (const ulonglong2*)sw0;  // [i*8 + c] : 4 hidden units
    const ulonglong2* sw1v = (const ulonglong2*)sw1;
    const u64* sb0p = (const u64*)sb0;
    const u64* sb1p = (const u64*)sb1;
    const u64* sw2p = (const u64*)sw2;

    // ---------------- Layer 0: 7 -> 32 (full width) ----------------
    u64 accA[16], accB[16];
#pragma unroll
    for (int p = 0; p < 16; ++p) { u64 bb = sb0p[p]; accA[p] = bb; accB[p] = bb; }
#pragma unroll
    for (int i = 0; i < NIN; ++i) {
        u64 xa = pk2(v[i], v[i]);
        u64 xb = pk2(v[7 + i], v[7 + i]);
#pragma unroll
        for (int c = 0; c < 8; ++c) {
            ulonglong2 w = sw0v[i * 8 + c];
            accA[2 * c]     = ffma2(w.x, xa, accA[2 * c]);
            accA[2 * c + 1] = ffma2(w.y, xa, accA[2 * c + 1]);
            accB[2 * c]     = ffma2(w.x, xb, accB[2 * c]);
            accB[2 * c + 1] = ffma2(w.y, xb, accB[2 * c + 1]);
        }
    }

    // tanh -> z (layer-0 acc registers die here; v dies here too)
    float zA[H], zB[H];
#pragma unroll
    for (int p = 0; p < 16; ++p) {
        float2 a = upk2(accA[p]);
        zA[2 * p] = tanh_approx(a.x); zA[2 * p + 1] = tanh_approx(a.y);
        float2 b = upk2(accB[p]);
        zB[2 * p] = tanh_approx(b.x); zB[2 * p + 1] = tanh_approx(b.y);
    }

    // ---- Layer 1 fused with Layer 2, in four quarters of 8 hidden units ----
    // Quarter-accumulators (4 u64 per sample = 16 regs total) die into the
    // layer-2 dot product at the end of each quarter. Total layer-1 shared
    // traffic is unchanged (each weight word read exactly once).
    u64 oA = pk2(0.0f, 0.0f);
    u64 oB = pk2(0.0f, 0.0f);

#pragma unroll
    for (int qtr = 0; qtr < 4; ++qtr) {
        u64 a1A[4], a1B[4];
#pragma unroll
        for (int p = 0; p < 4; ++p) {
            u64 bb = sb1p[qtr * 4 + p];
            a1A[p] = bb; a1B[p] = bb;
        }
#pragma unroll
        for (int i = 0; i < H; ++i) {
            u64 xa = pk2(zA[i], zA[i]);
            u64 xb = pk2(zB[i], zB[i]);
#pragma unroll
            for (int c = 0; c < 2; ++c) {
                ulonglong2 w = sw1v[i * 8 + qtr * 2 + c];
                a1A[2 * c]     = ffma2(w.x, xa, a1A[2 * c]);
                a1A[2 * c + 1] = ffma2(w.y, xa, a1A[2 * c + 1]);
                a1B[2 * c]     = ffma2(w.x, xb, a1B[2 * c]);
                a1B[2 * c + 1] = ffma2(w.y, xb, a1B[2 * c + 1]);
            }
        }
        // tanh + layer-2 partial dot (a1 dies here)
#pragma unroll
        for (int p = 0; p < 4; ++p) {
            u64 wp = sw2p[qtr * 4 + p];
            float2 a = upk2(a1A[p]);
            u64 za = pk2(tanh_approx(a.x), tanh_approx(a.y));
            oA = ffma2(wp, za, oA);
            float2 b = upk2(a1B[p]);
            u64 zb = pk2(tanh_approx(b.x), tanh_approx(b.y));
            oB = ffma2(wp, zb, oB);
        }
    }

    float2 ra = upk2(oA);
    float2 rb = upk2(oB);
    float bias2 = sb2s;
    float outA = ra.x + ra.y + bias2;
    float outB = rb.x + rb.y + bias2;

    ((float2*)out)[t] = make_float2(outA, outB);
}

extern "C" void kernel_launch(void* const* d_in, const int* in_sizes, int n_in,
                              void* d_out, int out_size)
{
    const float* q  = (const float*)d_in[0];
    const float* w0 = (const float*)d_in[1];
    const float* b0 = (const float*)d_in[2];
    const float* w1 = (const float*)d_in[3];
    const float* b1 = (const float*)d_in[4];
    const float* w2 = (const float*)d_in[5];
    const float* b2 = (const float*)d_in[6];
    float* out = (float*)d_out;

    const int B = in_sizes[0] / NIN;              // 2097152
    const int blocks = B / (TPB * SPT);           // 8192

    WarpTileMLP_kernel<<<blocks, TPB>>>(q, w0, b0, w1, b1, w2, b2, out);
}